// round 13
// baseline (speedup 1.0000x reference)
#include <cuda_runtime.h>
#include <cuda_fp16.h>
#include <math.h>
#include <stdint.h>

// ---------------- problem constants ----------------
#define BATCH 4
#define IMGH  64
#define IMGW  64
#define CDIM  768
#define WS    14
#define TOK   196
#define NH    12
#define HD    64
#define NWH   5
#define NWW   5
#define BW    100
#define ROWS_WIN 19600
#define ROWS_IMG 16384
#define QKVN  2304
#define FFN   3072

// ---------------- scratch ----------------
__device__ __half g_win[(size_t)ROWS_WIN * CDIM];
__device__ __half g_qkv[(size_t)ROWS_WIN * QKVN];
__device__ __half g_att[(size_t)ROWS_WIN * CDIM];
__device__ float  g_x2 [(size_t)ROWS_IMG * CDIM];
__device__ __half g_yln[(size_t)ROWS_IMG * CDIM];
__device__ __half g_y1 [(size_t)ROWS_IMG * FFN];
__device__ __half g_wqkv[(size_t)CDIM * QKVN];
__device__ __half g_wproj[(size_t)CDIM * CDIM];
__device__ __half g_wfc1[(size_t)CDIM * FFN];
__device__ __half g_wfc2[(size_t)FFN * CDIM];

// ---------------- helpers ----------------
__device__ __forceinline__ uint32_t smem_u32(const void* p) {
    uint32_t a;
    asm("{ .reg .u64 t; cvta.to.shared.u64 t, %1; cvt.u32.u64 %0, t; }" : "=r"(a) : "l"(p));
    return a;
}
__device__ __forceinline__ void cp16(void* sdst, const void* gsrc, int bytes) {
    uint32_t sa = smem_u32(sdst);
    asm volatile("cp.async.cg.shared.global [%0], [%1], 16, %2;" :: "r"(sa), "l"(gsrc), "r"(bytes));
}
#define CP_COMMIT() asm volatile("cp.async.commit_group;")

__device__ __forceinline__ void mma_f16(float c[4], const uint32_t a[4], const uint32_t b[2]) {
    asm volatile(
        "mma.sync.aligned.m16n8k16.row.col.f32.f16.f16.f32 "
        "{%0,%1,%2,%3}, {%4,%5,%6,%7}, {%8,%9}, {%0,%1,%2,%3};"
        : "+f"(c[0]), "+f"(c[1]), "+f"(c[2]), "+f"(c[3])
        : "r"(a[0]), "r"(a[1]), "r"(a[2]), "r"(a[3]), "r"(b[0]), "r"(b[1]));
}
__device__ __forceinline__ void ldmatrix_x4(uint32_t r[4], uint32_t addr) {
    asm volatile("ldmatrix.sync.aligned.m8n8.x4.shared.b16 {%0,%1,%2,%3}, [%4];"
                 : "=r"(r[0]), "=r"(r[1]), "=r"(r[2]), "=r"(r[3]) : "r"(addr));
}
__device__ __forceinline__ void ldmatrix_x2(uint32_t r[2], uint32_t addr) {
    asm volatile("ldmatrix.sync.aligned.m8n8.x2.shared.b16 {%0,%1}, [%2];"
                 : "=r"(r[0]), "=r"(r[1]) : "r"(addr));
}
__device__ __forceinline__ void ldmatrix_x2_trans(uint32_t r[2], uint32_t addr) {
    asm volatile("ldmatrix.sync.aligned.m8n8.x2.trans.shared.b16 {%0,%1}, [%2];"
                 : "=r"(r[0]), "=r"(r[1]) : "r"(addr));
}
__device__ __forceinline__ uint32_t packh2(float x, float y) {
    __half2 h = __floats2half2_rn(x, y);
    return *(uint32_t*)&h;
}

// ---------------- all weights -> half2 k-pair interleaved ----------------
#define W1T ((CDIM / 2) * QKVN)
#define W2T ((CDIM / 2) * CDIM)
#define W3T ((CDIM / 2) * FFN)
#define W4T ((FFN / 2) * CDIM)
__global__ void w2h_all_kernel(const float* __restrict__ wq, const float* __restrict__ wp,
                               const float* __restrict__ w1, const float* __restrict__ w2,
                               __half* __restrict__ oq, __half* __restrict__ op,
                               __half* __restrict__ o1, __half* __restrict__ o2) {
    int idx = blockIdx.x * blockDim.x + threadIdx.x;
    const float* in; __half* out; int Nd, local;
    if (idx < W1T)                    { in = wq; out = oq; Nd = QKVN; local = idx; }
    else if (idx < W1T + W2T)         { in = wp; out = op; Nd = CDIM; local = idx - W1T; }
    else if (idx < W1T + W2T + W3T)   { in = w1; out = o1; Nd = FFN;  local = idx - W1T - W2T; }
    else if (idx < W1T + W2T + W3T + W4T) { in = w2; out = o2; Nd = CDIM; local = idx - W1T - W2T - W3T; }
    else return;
    int kp = local / Nd, n = local % Nd;
    float a = in[(size_t)(2 * kp) * Nd + n];
    float b = in[(size_t)(2 * kp + 1) * Nd + n];
    ((__half2*)out)[local] = __floats2half2_rn(a, b);
}

// ---------------- LN1 + window partition -> half ----------------
__global__ void ln1_win_kernel(const float* __restrict__ x,
                               const float* __restrict__ g,
                               const float* __restrict__ b,
                               __half* __restrict__ out_) {
    int warp = (blockIdx.x * blockDim.x + threadIdx.x) >> 5;
    int lane = threadIdx.x & 31;
    if (warp >= ROWS_WIN) return;
    int r = warp;
    int bw = r / TOK, t = r % TOK;
    int bb = bw / (NWH * NWW), rem = bw % (NWH * NWW);
    int wh = rem / NWW, ww = rem % NWW;
    int i = t / WS, j = t % WS;
    int h = wh * WS + i, w = ww * WS + j;
    __half* out = out_ + (size_t)r * CDIM;
    if (h >= IMGH || w >= IMGW) {
        uint2 z = make_uint2(0u, 0u);
        #pragma unroll
        for (int q = 0; q < 6; q++) *(uint2*)(out + lane * 4 + q * 128) = z;
        return;
    }
    const float* row = x + ((size_t)(bb * IMGH + h) * IMGW + w) * CDIM;
    float v[24];
    float s = 0.f;
    #pragma unroll
    for (int q = 0; q < 6; q++) {
        float4 f = *(const float4*)(row + lane * 4 + q * 128);
        v[q*4+0] = f.x; v[q*4+1] = f.y; v[q*4+2] = f.z; v[q*4+3] = f.w;
        s += f.x + f.y + f.z + f.w;
    }
    #pragma unroll
    for (int o = 16; o > 0; o >>= 1) s += __shfl_xor_sync(0xffffffffu, s, o);
    float mean = s * (1.0f / CDIM);
    float ss = 0.f;
    #pragma unroll
    for (int q = 0; q < 24; q++) { float d = v[q] - mean; ss += d * d; }
    #pragma unroll
    for (int o = 16; o > 0; o >>= 1) ss += __shfl_xor_sync(0xffffffffu, ss, o);
    float rstd = rsqrtf(ss * (1.0f / CDIM) + 1e-6f);
    #pragma unroll
    for (int q = 0; q < 6; q++) {
        int c = lane * 4 + q * 128;
        float4 gg = *(const float4*)(g + c);
        float4 bb4 = *(const float4*)(b + c);
        __half2 h0 = __floats2half2_rn((v[q*4+0] - mean) * rstd * gg.x + bb4.x,
                                       (v[q*4+1] - mean) * rstd * gg.y + bb4.y);
        __half2 h1 = __floats2half2_rn((v[q*4+2] - mean) * rstd * gg.z + bb4.z,
                                       (v[q*4+3] - mean) * rstd * gg.w + bb4.w);
        *(__half2*)(out + c) = h0;
        *(__half2*)(out + c + 2) = h1;
    }
}

// ---------------- LN2 -> half ----------------
__global__ void ln2_kernel(const float* __restrict__ x,
                           const float* __restrict__ g,
                           const float* __restrict__ b,
                           __half* __restrict__ out_) {
    int warp = (blockIdx.x * blockDim.x + threadIdx.x) >> 5;
    int lane = threadIdx.x & 31;
    if (warp >= ROWS_IMG) return;
    const float* row = x + (size_t)warp * CDIM;
    __half* out = out_ + (size_t)warp * CDIM;
    float v[24];
    float s = 0.f;
    #pragma unroll
    for (int q = 0; q < 6; q++) {
        float4 f = *(const float4*)(row + lane * 4 + q * 128);
        v[q*4+0] = f.x; v[q*4+1] = f.y; v[q*4+2] = f.z; v[q*4+3] = f.w;
        s += f.x + f.y + f.z + f.w;
    }
    #pragma unroll
    for (int o = 16; o > 0; o >>= 1) s += __shfl_xor_sync(0xffffffffu, s, o);
    float mean = s * (1.0f / CDIM);
    float ss = 0.f;
    #pragma unroll
    for (int q = 0; q < 24; q++) { float d = v[q] - mean; ss += d * d; }
    #pragma unroll
    for (int o = 16; o > 0; o >>= 1) ss += __shfl_xor_sync(0xffffffffu, ss, o);
    float rstd = rsqrtf(ss * (1.0f / CDIM) + 1e-6f);
    #pragma unroll
    for (int q = 0; q < 6; q++) {
        int c = lane * 4 + q * 128;
        float4 gg = *(const float4*)(g + c);
        float4 bb4 = *(const float4*)(b + c);
        __half2 h0 = __floats2half2_rn((v[q*4+0] - mean) * rstd * gg.x + bb4.x,
                                       (v[q*4+1] - mean) * rstd * gg.y + bb4.y);
        __half2 h1 = __floats2half2_rn((v[q*4+2] - mean) * rstd * gg.z + bb4.z,
                                       (v[q*4+3] - mean) * rstd * gg.w + bb4.w);
        *(__half2*)(out + c) = h0;
        *(__half2*)(out + c + 2) = h1;
    }
}

// ---------------- FP16 mma.sync GEMM (k-slab 64, 3-stage, single-sync) ----------------
#define ASTRH 72
#define BSTR2 136
#define A_STAGE_B (128 * ASTRH * 2)
#define B_STAGE_B (32 * BSTR2 * 4)
#define NSTAGE 3
#define GEMM_SMEM_BYTES (NSTAGE * (A_STAGE_B + B_STAGE_B))

template<int EPI>
__global__ __launch_bounds__(256, 2)
void hgemm(const __half* __restrict__ A, const __half* __restrict__ B2,
           const float* __restrict__ bias, const float* __restrict__ R,
           void* __restrict__ Cc, int M, int N, int K) {
    extern __shared__ char smc[];
    __half* As = (__half*)smc;
    __half2* Bs = (__half2*)(smc + NSTAGE * A_STAGE_B);
    uint32_t As_u32 = smem_u32(As);

    int tid = threadIdx.x, wid = tid >> 5, lane = tid & 31;
    int g = lane >> 2, c = lane & 3;
    int mw = (wid >> 2) * 64, nw = (wid & 3) * 32;
    int m0 = blockIdx.y * 128, n0 = blockIdx.x * 128;

    float acc[4][4][4];
    #pragma unroll
    for (int i = 0; i < 4; i++)
        #pragma unroll
        for (int j = 0; j < 4; j++)
            #pragma unroll
            for (int q = 0; q < 4; q++) acc[i][j][q] = 0.f;

    int arow = tid >> 2, achk = (tid & 3) * 16;
    int bkrow = tid >> 3, bseg = (tid & 7) * 16;

    uint32_t a_lm_off = (uint32_t)((mw + (lane & 15)) * ASTRH + (lane >> 4) * 8) * 2;

    auto loadStage = [&](int t) {
        int st = t % NSTAGE;
        __half* Ad = As + (size_t)st * 128 * ASTRH;
        #pragma unroll
        for (int p = 0; p < 2; p++) {
            int r = arow + p * 64;
            int m = m0 + r;
            bool v = m < M;
            const __half* src = v ? (A + (size_t)m * K + t * 64 + achk) : A;
            cp16(Ad + r * ASTRH + achk,     src,             v ? 16 : 0);
            cp16(Ad + r * ASTRH + achk + 8, v ? src + 8 : A, v ? 16 : 0);
        }
        __half2* Bd = Bs + (size_t)st * 32 * BSTR2;
        const __half2* bsrc = (const __half2*)B2 + (size_t)(t * 32 + bkrow) * N + n0 + bseg;
        #pragma unroll
        for (int i = 0; i < 4; i++)
            cp16(Bd + bkrow * BSTR2 + bseg + 4 * i, bsrc + 4 * i, 16);
        CP_COMMIT();
    };

    int nk = K / 64;
    #pragma unroll
    for (int t = 0; t < NSTAGE - 1; t++) loadStage(t);

    for (int t = 0; t < nk; t++) {
        asm volatile("cp.async.wait_group %0;" :: "n"(NSTAGE - 2) : "memory");
        __syncthreads();
        if (t + NSTAGE - 1 < nk) loadStage(t + NSTAGE - 1);
        else CP_COMMIT();
        uint32_t a_base = As_u32 + (uint32_t)((t % NSTAGE) * A_STAGE_B) + a_lm_off;
        const __half2* b_s = Bs + (size_t)(t % NSTAGE) * 32 * BSTR2;
        #pragma unroll
        for (int kk = 0; kk < 4; kk++) {
            uint32_t af[4][4], bf[4][2];
            #pragma unroll
            for (int tm = 0; tm < 4; tm++)
                ldmatrix_x4(af[tm], a_base + (uint32_t)(tm * 16 * ASTRH + kk * 16) * 2);
            #pragma unroll
            for (int tn = 0; tn < 4; tn++) {
                const __half2* bp = b_s + (kk * 8 + c) * BSTR2 + nw + tn * 8 + g;
                bf[tn][0] = *(const uint32_t*)(bp);
                bf[tn][1] = *(const uint32_t*)(bp + 4 * BSTR2);
            }
            #pragma unroll
            for (int tm = 0; tm < 4; tm++)
                #pragma unroll
                for (int tn = 0; tn < 4; tn++)
                    mma_f16(acc[tm][tn], af[tm], bf[tn]);
        }
    }

    #pragma unroll
    for (int tm = 0; tm < 4; tm++) {
        #pragma unroll
        for (int half_ = 0; half_ < 2; half_++) {
            int m = m0 + mw + tm * 16 + g + half_ * 8;
            if (m >= M) continue;
            size_t obase = 0;
            const float* rbase = nullptr;
            bool valid = true;
            if (EPI == 2) {
                int bw = m / TOK, tt = m % TOK;
                int bb = bw / (NWH * NWW), rem = bw % (NWH * NWW);
                int wh = rem / NWW, ww = rem % NWW;
                int ii = tt / WS, jj = tt % WS;
                int h = wh * WS + ii, w = ww * WS + jj;
                if (h >= IMGH || w >= IMGW) valid = false;
                else { obase = ((size_t)(bb * IMGH + h) * IMGW + w) * CDIM; rbase = R + obase; }
            } else {
                obase = (size_t)m * N;
                if (EPI == 3) rbase = R + obase;
            }
            if (!valid) continue;
            #pragma unroll
            for (int tn = 0; tn < 4; tn++) {
                int n = n0 + nw + tn * 8 + 2 * c;
                float v0 = acc[tm][tn][half_ * 2 + 0] + bias[n];
                float v1 = acc[tm][tn][half_ * 2 + 1] + bias[n + 1];
                if (EPI == 0) {
                    *(__half2*)((__half*)Cc + obase + n) = __floats2half2_rn(v0, v1);
                } else if (EPI == 1) {
                    v0 = 0.5f * v0 * (1.0f + erff(v0 * 0.7071067811865476f));
                    v1 = 0.5f * v1 * (1.0f + erff(v1 * 0.7071067811865476f));
                    *(__half2*)((__half*)Cc + obase + n) = __floats2half2_rn(v0, v1);
                } else {
                    v0 += rbase[n];
                    v1 += rbase[n + 1];
                    *(float2*)((float*)Cc + obase + n) = make_float2(v0, v1);
                }
            }
        }
    }
}

// ---------------- tensor-core windowed attention v2 ----------------
// 1 CTA per (window, head). 8 warps = 4 pairs; pair handles one 16-row m-tile per
// round, n-dim split between the 2 warps (nt 0-13 / 14-25). S C-fragments are
// reused directly as P A-fragments (no P smem). Q/K/V in swizzled 128B rows.
#define QSWB(t, b) (((t) << 7) + ((b) ^ (((t) & 7) << 4)))
#define A3_Q   0          // 208*128 = 26624
#define A3_K   26624
#define A3_V   53248
#define A3_RH  79872      // half [208][16] = 6656
#define A3_RW  86528
#define A3_OEX 93184      // float [4][16][64] = 16384
#define A3_MXE 109568     // float [4][2][16] = 512
#define A3_SME 110080     // float [4][2][16] = 512
#define ATTN_SMEM_BYTES 110592

__global__ __launch_bounds__(256, 2)
void attn_mma_kernel(const __half* __restrict__ qkv,
                     const float* __restrict__ relh,
                     const float* __restrict__ relw,
                     __half* __restrict__ attout) {
    extern __shared__ char smc[];
    __half* RHh = (__half*)(smc + A3_RH);
    __half* RWh = (__half*)(smc + A3_RW);
    float* MXE = (float*)(smc + A3_MXE);
    float* SME = (float*)(smc + A3_SME);

    int blk = blockIdx.x;
    int bw = blk / NH, nh = blk % NH;
    int tid = threadIdx.x, lane = tid & 31, warp = tid >> 5;
    int g = lane >> 2, c = lane & 3;
    int pair = warp >> 1, halfw = warp & 1;

    uint32_t Qs_u = smem_u32(smc + A3_Q);
    uint32_t Ks_u = smem_u32(smc + A3_K);
    uint32_t Vs_u = smem_u32(smc + A3_V);

    // ---- load q/k/v swizzled; zero pad rows 196..207 ----
    const __half* base = qkv + (size_t)bw * TOK * QKVN + nh * HD;
    for (int t4 = tid; t4 < TOK * 8; t4 += 256) {
        int t = t4 >> 3, cb = (t4 & 7) * 16;
        const __half* p = base + (size_t)t * QKVN + cb / 2;
        *(uint4*)(smc + A3_Q + QSWB(t, cb)) = *(const uint4*)(p);
        *(uint4*)(smc + A3_K + QSWB(t, cb)) = *(const uint4*)(p + CDIM);
        *(uint4*)(smc + A3_V + QSWB(t, cb)) = *(const uint4*)(p + 2 * CDIM);
    }
    for (int i = tid; i < 12 * 8; i += 256) {
        int t = TOK + i / 8, cb = (i % 8) * 16;
        uint4 z = make_uint4(0, 0, 0, 0);
        *(uint4*)(smc + A3_Q + QSWB(t, cb)) = z;
        *(uint4*)(smc + A3_K + QSWB(t, cb)) = z;
        *(uint4*)(smc + A3_V + QSWB(t, cb)) = z;
    }
    __syncthreads();

    // ---- decomposed rel-pos -> half tables ----
    for (int qi = warp; qi < TOK; qi += 8) {
        int i = qi / WS, j = qi % WS;
        bool doRH = lane < WS;
        bool doRW = (lane >= 16) && (lane < 16 + WS);
        if (doRH || doRW) {
            const float* tab = doRH ? (relh + (size_t)(i - lane + WS - 1) * HD)
                                    : (relw + (size_t)(j - (lane - 16) + WS - 1) * HD);
            float a = 0.f;
            #pragma unroll
            for (int cb = 0; cb < 8; cb++) {
                uint4 qv = *(const uint4*)(smc + A3_Q + QSWB(qi, cb * 16));
                const __half2* qh = (const __half2*)&qv;
                #pragma unroll
                for (int u = 0; u < 4; u++) {
                    float2 qf = __half22float2(qh[u]);
                    float2 tf = *(const float2*)(tab + cb * 8 + u * 2);
                    a = fmaf(qf.x, tf.x, fmaf(qf.y, tf.y, a));
                }
            }
            if (doRH) RHh[qi * 16 + lane] = __float2half_rn(a);
            else      RWh[qi * 16 + (lane - 16)] = __float2half_rn(a);
        }
    }
    __syncthreads();

    const float scale = 0.125f;
    int ntl = halfw ? 12 : 14;
    int ntbase = halfw ? 14 : 0;
    int ktl = halfw ? 6 : 7;
    float* Oexp = (float*)(smc + A3_OEX) + pair * 1024;
    int xown = (pair * 2 + halfw) * 16;
    int xoth = (pair * 2 + 1 - halfw) * 16;

    for (int r = 0; r < 4; r++) {
        int mt = r * 4 + pair;
        bool active = mt < 13;
        int m0 = mt * 16;
        int qi0 = m0 + g, qi1 = qi0 + 8;

        float acc[14][4];
        float mx0 = -1e30f, mx1 = -1e30f;

        if (active) {
            #pragma unroll
            for (int j = 0; j < 14; j++)
                #pragma unroll
                for (int q = 0; q < 4; q++) acc[j][q] = 0.f;

            // ---- S = Q K^T (this warp's n-half) ----
            #pragma unroll
            for (int ks = 0; ks < 4; ks++) {
                uint32_t af[4];
                ldmatrix_x4(af, Qs_u + QSWB(m0 + (lane & 15), (lane >> 4) * 16 + ks * 32));
                #pragma unroll
                for (int j = 0; j < 14; j++) {
                    if (j < ntl) {
                        int nt = ntbase + j;
                        uint32_t bf[2];
                        ldmatrix_x2(bf, Ks_u + QSWB(nt * 8 + (lane & 7),
                                                    ks * 32 + ((lane >> 3) & 1) * 16));
                        mma_f16(acc[j], af, bf);
                    }
                }
            }

            // ---- bias + local max ----
            #pragma unroll
            for (int j = 0; j < 14; j++) {
                if (j < ntl) {
                    int n = (ntbase + j) * 8 + 2 * c;
                    int n2 = n + 1;
                    if (n < TOK) {
                        int kk = n / WS, ll = n % WS;
                        acc[j][0] = acc[j][0] * scale + __half2float(RHh[qi0 * 16 + kk]) + __half2float(RWh[qi0 * 16 + ll]);
                        acc[j][2] = acc[j][2] * scale + __half2float(RHh[qi1 * 16 + kk]) + __half2float(RWh[qi1 * 16 + ll]);
                    } else { acc[j][0] = -1e30f; acc[j][2] = -1e30f; }
                    if (n2 < TOK) {
                        int kk = n2 / WS, ll = n2 % WS;
                        acc[j][1] = acc[j][1] * scale + __half2float(RHh[qi0 * 16 + kk]) + __half2float(RWh[qi0 * 16 + ll]);
                        acc[j][3] = acc[j][3] * scale + __half2float(RHh[qi1 * 16 + kk]) + __half2float(RWh[qi1 * 16 + ll]);
                    } else { acc[j][1] = -1e30f; acc[j][3] = -1e30f; }
                } else {
                    acc[j][0] = acc[j][1] = acc[j][2] = acc[j][3] = -1e30f;
                }
                mx0 = fmaxf(mx0, fmaxf(acc[j][0], acc[j][1]));
                mx1 = fmaxf(mx1, fmaxf(acc[j][2], acc[j][3]));
            }
            #pragma unroll
            for (int o = 1; o <= 2; o <<= 1) {
                mx0 = fmaxf(mx0, __shfl_xor_sync(0xffffffffu, mx0, o));
                mx1 = fmaxf(mx1, __shfl_xor_sync(0xffffffffu, mx1, o));
            }
            if (c == 0) { MXE[xown + g] = mx0; MXE[xown + g + 8] = mx1; }
        }
        __syncthreads();

        float sum0 = 0.f, sum1 = 0.f;
        if (active) {
            mx0 = fmaxf(mx0, MXE[xoth + g]);
            mx1 = fmaxf(mx1, MXE[xoth + g + 8]);
            #pragma unroll
            for (int j = 0; j < 14; j++) {
                acc[j][0] = __expf(acc[j][0] - mx0);
                acc[j][1] = __expf(acc[j][1] - mx0);
                acc[j][2] = __expf(acc[j][2] - mx1);
                acc[j][3] = __expf(acc[j][3] - mx1);
                sum0 += acc[j][0] + acc[j][1];
                sum1 += acc[j][2] + acc[j][3];
            }
            #pragma unroll
            for (int o = 1; o <= 2; o <<= 1) {
                sum0 += __shfl_xor_sync(0xffffffffu, sum0, o);
                sum1 += __shfl_xor_sync(0xffffffffu, sum1, o);
            }
            if (c == 0) { SME[xown + g] = sum0; SME[xown + g + 8] = sum1; }
        }
        __syncthreads();

        float acc2[8][4];
        if (active) {
            float inv0 = __frcp_rn(sum0 + SME[xoth + g]);
            float inv1 = __frcp_rn(sum1 + SME[xoth + g + 8]);

            // convert S fragments -> P A-fragments (in registers)
            uint32_t p0[14], p1[14];
            #pragma unroll
            for (int j = 0; j < 14; j++) {
                p0[j] = packh2(acc[j][0] * inv0, acc[j][1] * inv0);
                p1[j] = packh2(acc[j][2] * inv1, acc[j][3] * inv1);
            }

            #pragma unroll
            for (int nt2 = 0; nt2 < 8; nt2++)
                #pragma unroll
                for (int q = 0; q < 4; q++) acc2[nt2][q] = 0.f;

            #pragma unroll
            for (int kl = 0; kl < 7; kl++) {
                if (kl < ktl) {
                    int ktg = halfw * 7 + kl;
                    uint32_t a[4] = { p0[2 * kl], p1[2 * kl], p0[2 * kl + 1], p1[2 * kl + 1] };
                    #pragma unroll
                    for (int nt2 = 0; nt2 < 8; nt2++) {
                        uint32_t bf[2];
                        ldmatrix_x2_trans(bf, Vs_u + QSWB(16 * ktg + (lane & 7) + ((lane >> 3) & 1) * 8,
                                                          nt2 * 16));
                        mma_f16(acc2[nt2], a, bf);
                    }
                }
            }
            if (halfw) {
                #pragma unroll
                for (int nt2 = 0; nt2 < 8; nt2++) {
                    *(float2*)(Oexp + g * 64 + nt2 * 8 + 2 * c)       = make_float2(acc2[nt2][0], acc2[nt2][1]);
                    *(float2*)(Oexp + (g + 8) * 64 + nt2 * 8 + 2 * c) = make_float2(acc2[nt2][2], acc2[nt2][3]);
                }
            }
        }
        __syncthreads();

        if (active && !halfw) {
            __half* orow0 = attout + ((size_t)(bw * TOK + qi0)) * CDIM + nh * HD;
            __half* orow1 = attout + ((size_t)(bw * TOK + qi1)) * CDIM + nh * HD;
            #pragma unroll
            for (int nt2 = 0; nt2 < 8; nt2++) {
                float o0 = acc2[nt2][0] + Oexp[g * 64 + nt2 * 8 + 2 * c];
                float o1 = acc2[nt2][1] + Oexp[g * 64 + nt2 * 8 + 2 * c + 1];
                float o2 = acc2[nt2][2] + Oexp[(g + 8) * 64 + nt2 * 8 + 2 * c];
                float o3 = acc2[nt2][3] + Oexp[(g + 8) * 64 + nt2 * 8 + 2 * c + 1];
                if (qi0 < TOK) *(__half2*)(orow0 + nt2 * 8 + 2 * c) = __floats2half2_rn(o0, o1);
                if (qi1 < TOK) *(__half2*)(orow1 + nt2 * 8 + 2 * c) = __floats2half2_rn(o2, o3);
            }
        }
    }
}

// ---------------- launch ----------------
extern "C" void kernel_launch(void* const* d_in, const int* in_sizes, int n_in,
                              void* d_out, int out_size) {
    const float* x       = (const float*)d_in[0];
    const float* ln1_g   = (const float*)d_in[1];
    const float* ln1_b   = (const float*)d_in[2];
    const float* w_qkv   = (const float*)d_in[3];
    const float* b_qkv   = (const float*)d_in[4];
    const float* w_proj  = (const float*)d_in[5];
    const float* b_proj  = (const float*)d_in[6];
    const float* relh    = (const float*)d_in[7];
    const float* relw    = (const float*)d_in[8];
    const float* ln2_g   = (const float*)d_in[9];
    const float* ln2_b   = (const float*)d_in[10];
    const float* w_fc1   = (const float*)d_in[11];
    const float* b_fc1   = (const float*)d_in[12];
    const float* w_fc2   = (const float*)d_in[13];
    const float* b_fc2   = (const float*)d_in[14];
    float* out = (float*)d_out;

    __half *win, *qkv, *att, *yln, *y1, *wqkv, *wproj, *wfc1, *wfc2;
    float *x2;
    cudaGetSymbolAddress((void**)&win, g_win);
    cudaGetSymbolAddress((void**)&qkv, g_qkv);
    cudaGetSymbolAddress((void**)&att, g_att);
    cudaGetSymbolAddress((void**)&x2,  g_x2);
    cudaGetSymbolAddress((void**)&yln, g_yln);
    cudaGetSymbolAddress((void**)&y1,  g_y1);
    cudaGetSymbolAddress((void**)&wqkv,  g_wqkv);
    cudaGetSymbolAddress((void**)&wproj, g_wproj);
    cudaGetSymbolAddress((void**)&wfc1,  g_wfc1);
    cudaGetSymbolAddress((void**)&wfc2,  g_wfc2);

    cudaFuncSetAttribute(attn_mma_kernel, cudaFuncAttributeMaxDynamicSharedMemorySize, ATTN_SMEM_BYTES);
    cudaFuncSetAttribute(hgemm<0>, cudaFuncAttributeMaxDynamicSharedMemorySize, GEMM_SMEM_BYTES);
    cudaFuncSetAttribute(hgemm<1>, cudaFuncAttributeMaxDynamicSharedMemorySize, GEMM_SMEM_BYTES);
    cudaFuncSetAttribute(hgemm<2>, cudaFuncAttributeMaxDynamicSharedMemorySize, GEMM_SMEM_BYTES);
    cudaFuncSetAttribute(hgemm<3>, cudaFuncAttributeMaxDynamicSharedMemorySize, GEMM_SMEM_BYTES);

    // (1) weights -> half2 interleaved
    int wtot = W1T + W2T + W3T + W4T;
    w2h_all_kernel<<<(wtot + 255) / 256, 256>>>(w_qkv, w_proj, w_fc1, w_fc2,
                                                wqkv, wproj, wfc1, wfc2);

    // (2) LN1 + window partition
    ln1_win_kernel<<<(ROWS_WIN * 32 + 255) / 256, 256>>>(x, ln1_g, ln1_b, win);

    // (3) QKV GEMM -> half
    hgemm<0><<<dim3(QKVN / 128, (ROWS_WIN + 127) / 128), 256, GEMM_SMEM_BYTES>>>(
        win, wqkv, b_qkv, nullptr, qkv, ROWS_WIN, QKVN, CDIM);

    // (4) attention (tensor cores, v2)
    attn_mma_kernel<<<BW * NH, 256, ATTN_SMEM_BYTES>>>(qkv, relh, relw, att);

    // (5) proj + window reverse + residual -> f32
    hgemm<2><<<dim3(CDIM / 128, (ROWS_WIN + 127) / 128), 256, GEMM_SMEM_BYTES>>>(
        att, wproj, b_proj, x, x2, ROWS_WIN, CDIM, CDIM);

    // (6) LN2 -> half
    ln2_kernel<<<(ROWS_IMG * 32 + 255) / 256, 256>>>(x2, ln2_g, ln2_b, yln);

    // (7) fc1 + gelu -> half
    hgemm<1><<<dim3(FFN / 128, ROWS_IMG / 128), 256, GEMM_SMEM_BYTES>>>(
        yln, wfc1, b_fc1, nullptr, y1, ROWS_IMG, FFN, CDIM);

    // (8) fc2 + residual -> out f32
    hgemm<3><<<dim3(CDIM / 128, ROWS_IMG / 128), 256, GEMM_SMEM_BYTES>>>(
        y1, wfc2, b_fc2, x2, out, ROWS_IMG, CDIM, FFN);
}

// round 15
// speedup vs baseline: 1.2692x; 1.2692x over previous
#include <cuda_runtime.h>
#include <cuda_fp16.h>
#include <math.h>
#include <stdint.h>

// ---------------- problem constants ----------------
#define BATCH 4
#define IMGH  64
#define IMGW  64
#define CDIM  768
#define WS    14
#define TOK   196
#define NH    12
#define HD    64
#define NWH   5
#define NWW   5
#define BW    100
#define ROWS_WIN 19600
#define ROWS_IMG 16384
#define QKVN  2304
#define FFN   3072

// ---------------- scratch ----------------
__device__ __half g_win[(size_t)ROWS_WIN * CDIM];
__device__ __half g_qkv[(size_t)ROWS_WIN * QKVN];
__device__ __half g_att[(size_t)ROWS_WIN * CDIM];
__device__ float  g_x2 [(size_t)ROWS_IMG * CDIM];
__device__ __half g_yln[(size_t)ROWS_IMG * CDIM];
__device__ __half g_y1 [(size_t)ROWS_IMG * FFN];
__device__ __half g_wqkv[(size_t)CDIM * QKVN];
__device__ __half g_wproj[(size_t)CDIM * CDIM];
__device__ __half g_wfc1[(size_t)CDIM * FFN];
__device__ __half g_wfc2[(size_t)FFN * CDIM];

// ---------------- helpers ----------------
__device__ __forceinline__ uint32_t smem_u32(const void* p) {
    uint32_t a;
    asm("{ .reg .u64 t; cvta.to.shared.u64 t, %1; cvt.u32.u64 %0, t; }" : "=r"(a) : "l"(p));
    return a;
}
__device__ __forceinline__ void cp16(void* sdst, const void* gsrc, int bytes) {
    uint32_t sa = smem_u32(sdst);
    asm volatile("cp.async.cg.shared.global [%0], [%1], 16, %2;" :: "r"(sa), "l"(gsrc), "r"(bytes));
}
#define CP_COMMIT() asm volatile("cp.async.commit_group;")

__device__ __forceinline__ void mma_f16(float c[4], const uint32_t a[4], const uint32_t b[2]) {
    asm volatile(
        "mma.sync.aligned.m16n8k16.row.col.f32.f16.f16.f32 "
        "{%0,%1,%2,%3}, {%4,%5,%6,%7}, {%8,%9}, {%0,%1,%2,%3};"
        : "+f"(c[0]), "+f"(c[1]), "+f"(c[2]), "+f"(c[3])
        : "r"(a[0]), "r"(a[1]), "r"(a[2]), "r"(a[3]), "r"(b[0]), "r"(b[1]));
}
__device__ __forceinline__ void ldmatrix_x4(uint32_t r[4], uint32_t addr) {
    asm volatile("ldmatrix.sync.aligned.m8n8.x4.shared.b16 {%0,%1,%2,%3}, [%4];"
                 : "=r"(r[0]), "=r"(r[1]), "=r"(r[2]), "=r"(r[3]) : "r"(addr));
}

// ---------------- all weights -> half2 k-pair interleaved ----------------
#define W1T ((CDIM / 2) * QKVN)
#define W2T ((CDIM / 2) * CDIM)
#define W3T ((CDIM / 2) * FFN)
#define W4T ((FFN / 2) * CDIM)
__global__ void w2h_all_kernel(const float* __restrict__ wq, const float* __restrict__ wp,
                               const float* __restrict__ w1, const float* __restrict__ w2,
                               __half* __restrict__ oq, __half* __restrict__ op,
                               __half* __restrict__ o1, __half* __restrict__ o2) {
    int idx = blockIdx.x * blockDim.x + threadIdx.x;
    const float* in; __half* out; int Nd, local;
    if (idx < W1T)                    { in = wq; out = oq; Nd = QKVN; local = idx; }
    else if (idx < W1T + W2T)         { in = wp; out = op; Nd = CDIM; local = idx - W1T; }
    else if (idx < W1T + W2T + W3T)   { in = w1; out = o1; Nd = FFN;  local = idx - W1T - W2T; }
    else if (idx < W1T + W2T + W3T + W4T) { in = w2; out = o2; Nd = CDIM; local = idx - W1T - W2T - W3T; }
    else return;
    int kp = local / Nd, n = local % Nd;
    float a = in[(size_t)(2 * kp) * Nd + n];
    float b = in[(size_t)(2 * kp + 1) * Nd + n];
    ((__half2*)out)[local] = __floats2half2_rn(a, b);
}

// ---------------- LN1 + window partition -> half ----------------
__global__ void ln1_win_kernel(const float* __restrict__ x,
                               const float* __restrict__ g,
                               const float* __restrict__ b,
                               __half* __restrict__ out_) {
    int warp = (blockIdx.x * blockDim.x + threadIdx.x) >> 5;
    int lane = threadIdx.x & 31;
    if (warp >= ROWS_WIN) return;
    int r = warp;
    int bw = r / TOK, t = r % TOK;
    int bb = bw / (NWH * NWW), rem = bw % (NWH * NWW);
    int wh = rem / NWW, ww = rem % NWW;
    int i = t / WS, j = t % WS;
    int h = wh * WS + i, w = ww * WS + j;
    __half* out = out_ + (size_t)r * CDIM;
    if (h >= IMGH || w >= IMGW) {
        uint2 z = make_uint2(0u, 0u);
        #pragma unroll
        for (int q = 0; q < 6; q++) *(uint2*)(out + lane * 4 + q * 128) = z;
        return;
    }
    const float* row = x + ((size_t)(bb * IMGH + h) * IMGW + w) * CDIM;
    float v[24];
    float s = 0.f;
    #pragma unroll
    for (int q = 0; q < 6; q++) {
        float4 f = *(const float4*)(row + lane * 4 + q * 128);
        v[q*4+0] = f.x; v[q*4+1] = f.y; v[q*4+2] = f.z; v[q*4+3] = f.w;
        s += f.x + f.y + f.z + f.w;
    }
    #pragma unroll
    for (int o = 16; o > 0; o >>= 1) s += __shfl_xor_sync(0xffffffffu, s, o);
    float mean = s * (1.0f / CDIM);
    float ss = 0.f;
    #pragma unroll
    for (int q = 0; q < 24; q++) { float d = v[q] - mean; ss += d * d; }
    #pragma unroll
    for (int o = 16; o > 0; o >>= 1) ss += __shfl_xor_sync(0xffffffffu, ss, o);
    float rstd = rsqrtf(ss * (1.0f / CDIM) + 1e-6f);
    #pragma unroll
    for (int q = 0; q < 6; q++) {
        int c = lane * 4 + q * 128;
        float4 gg = *(const float4*)(g + c);
        float4 bb4 = *(const float4*)(b + c);
        __half2 h0 = __floats2half2_rn((v[q*4+0] - mean) * rstd * gg.x + bb4.x,
                                       (v[q*4+1] - mean) * rstd * gg.y + bb4.y);
        __half2 h1 = __floats2half2_rn((v[q*4+2] - mean) * rstd * gg.z + bb4.z,
                                       (v[q*4+3] - mean) * rstd * gg.w + bb4.w);
        *(__half2*)(out + c) = h0;
        *(__half2*)(out + c + 2) = h1;
    }
}

// ---------------- LN2 -> half ----------------
__global__ void ln2_kernel(const float* __restrict__ x,
                           const float* __restrict__ g,
                           const float* __restrict__ b,
                           __half* __restrict__ out_) {
    int warp = (blockIdx.x * blockDim.x + threadIdx.x) >> 5;
    int lane = threadIdx.x & 31;
    if (warp >= ROWS_IMG) return;
    const float* row = x + (size_t)warp * CDIM;
    __half* out = out_ + (size_t)warp * CDIM;
    float v[24];
    float s = 0.f;
    #pragma unroll
    for (int q = 0; q < 6; q++) {
        float4 f = *(const float4*)(row + lane * 4 + q * 128);
        v[q*4+0] = f.x; v[q*4+1] = f.y; v[q*4+2] = f.z; v[q*4+3] = f.w;
        s += f.x + f.y + f.z + f.w;
    }
    #pragma unroll
    for (int o = 16; o > 0; o >>= 1) s += __shfl_xor_sync(0xffffffffu, s, o);
    float mean = s * (1.0f / CDIM);
    float ss = 0.f;
    #pragma unroll
    for (int q = 0; q < 24; q++) { float d = v[q] - mean; ss += d * d; }
    #pragma unroll
    for (int o = 16; o > 0; o >>= 1) ss += __shfl_xor_sync(0xffffffffu, ss, o);
    float rstd = rsqrtf(ss * (1.0f / CDIM) + 1e-6f);
    #pragma unroll
    for (int q = 0; q < 6; q++) {
        int c = lane * 4 + q * 128;
        float4 gg = *(const float4*)(g + c);
        float4 bb4 = *(const float4*)(b + c);
        __half2 h0 = __floats2half2_rn((v[q*4+0] - mean) * rstd * gg.x + bb4.x,
                                       (v[q*4+1] - mean) * rstd * gg.y + bb4.y);
        __half2 h1 = __floats2half2_rn((v[q*4+2] - mean) * rstd * gg.z + bb4.z,
                                       (v[q*4+3] - mean) * rstd * gg.w + bb4.w);
        *(__half2*)(out + c) = h0;
        *(__half2*)(out + c + 2) = h1;
    }
}

// ---------------- FP16 mma.sync GEMM (k-slab 64, 3-stage, single-sync) ----------------
#define ASTRH 72
#define BSTR2 136
#define A_STAGE_B (128 * ASTRH * 2)
#define B_STAGE_B (32 * BSTR2 * 4)
#define NSTAGE 3
#define GEMM_SMEM_BYTES (NSTAGE * (A_STAGE_B + B_STAGE_B))

template<int EPI>
__global__ __launch_bounds__(256, 2)
void hgemm(const __half* __restrict__ A, const __half* __restrict__ B2,
           const float* __restrict__ bias, const float* __restrict__ R,
           void* __restrict__ Cc, int M, int N, int K) {
    extern __shared__ char smc[];
    __half* As = (__half*)smc;
    __half2* Bs = (__half2*)(smc + NSTAGE * A_STAGE_B);
    uint32_t As_u32 = smem_u32(As);

    int tid = threadIdx.x, wid = tid >> 5, lane = tid & 31;
    int g = lane >> 2, c = lane & 3;
    int mw = (wid >> 2) * 64, nw = (wid & 3) * 32;
    int m0 = blockIdx.y * 128, n0 = blockIdx.x * 128;

    float acc[4][4][4];
    #pragma unroll
    for (int i = 0; i < 4; i++)
        #pragma unroll
        for (int j = 0; j < 4; j++)
            #pragma unroll
            for (int q = 0; q < 4; q++) acc[i][j][q] = 0.f;

    int arow = tid >> 2, achk = (tid & 3) * 16;
    int bkrow = tid >> 3, bseg = (tid & 7) * 16;

    uint32_t a_lm_off = (uint32_t)((mw + (lane & 15)) * ASTRH + (lane >> 4) * 8) * 2;

    auto loadStage = [&](int t) {
        int st = t % NSTAGE;
        __half* Ad = As + (size_t)st * 128 * ASTRH;
        #pragma unroll
        for (int p = 0; p < 2; p++) {
            int r = arow + p * 64;
            int m = m0 + r;
            bool v = m < M;
            const __half* src = v ? (A + (size_t)m * K + t * 64 + achk) : A;
            cp16(Ad + r * ASTRH + achk,     src,             v ? 16 : 0);
            cp16(Ad + r * ASTRH + achk + 8, v ? src + 8 : A, v ? 16 : 0);
        }
        __half2* Bd = Bs + (size_t)st * 32 * BSTR2;
        const __half2* bsrc = (const __half2*)B2 + (size_t)(t * 32 + bkrow) * N + n0 + bseg;
        #pragma unroll
        for (int i = 0; i < 4; i++)
            cp16(Bd + bkrow * BSTR2 + bseg + 4 * i, bsrc + 4 * i, 16);
        CP_COMMIT();
    };

    int nk = K / 64;
    #pragma unroll
    for (int t = 0; t < NSTAGE - 1; t++) loadStage(t);

    for (int t = 0; t < nk; t++) {
        asm volatile("cp.async.wait_group %0;" :: "n"(NSTAGE - 2) : "memory");
        __syncthreads();
        if (t + NSTAGE - 1 < nk) loadStage(t + NSTAGE - 1);
        else CP_COMMIT();
        uint32_t a_base = As_u32 + (uint32_t)((t % NSTAGE) * A_STAGE_B) + a_lm_off;
        const __half2* b_s = Bs + (size_t)(t % NSTAGE) * 32 * BSTR2;
        #pragma unroll
        for (int kk = 0; kk < 4; kk++) {
            uint32_t af[4][4], bf[4][2];
            #pragma unroll
            for (int tm = 0; tm < 4; tm++)
                ldmatrix_x4(af[tm], a_base + (uint32_t)(tm * 16 * ASTRH + kk * 16) * 2);
            #pragma unroll
            for (int tn = 0; tn < 4; tn++) {
                const __half2* bp = b_s + (kk * 8 + c) * BSTR2 + nw + tn * 8 + g;
                bf[tn][0] = *(const uint32_t*)(bp);
                bf[tn][1] = *(const uint32_t*)(bp + 4 * BSTR2);
            }
            #pragma unroll
            for (int tm = 0; tm < 4; tm++)
                #pragma unroll
                for (int tn = 0; tn < 4; tn++)
                    mma_f16(acc[tm][tn], af[tm], bf[tn]);
        }
    }

    #pragma unroll
    for (int tm = 0; tm < 4; tm++) {
        #pragma unroll
        for (int half_ = 0; half_ < 2; half_++) {
            int m = m0 + mw + tm * 16 + g + half_ * 8;
            if (m >= M) continue;
            size_t obase = 0;
            const float* rbase = nullptr;
            bool valid = true;
            if (EPI == 2) {
                int bw = m / TOK, tt = m % TOK;
                int bb = bw / (NWH * NWW), rem = bw % (NWH * NWW);
                int wh = rem / NWW, ww = rem % NWW;
                int ii = tt / WS, jj = tt % WS;
                int h = wh * WS + ii, w = ww * WS + jj;
                if (h >= IMGH || w >= IMGW) valid = false;
                else { obase = ((size_t)(bb * IMGH + h) * IMGW + w) * CDIM; rbase = R + obase; }
            } else {
                obase = (size_t)m * N;
                if (EPI == 3) rbase = R + obase;
            }
            if (!valid) continue;
            #pragma unroll
            for (int tn = 0; tn < 4; tn++) {
                int n = n0 + nw + tn * 8 + 2 * c;
                float v0 = acc[tm][tn][half_ * 2 + 0] + bias[n];
                float v1 = acc[tm][tn][half_ * 2 + 1] + bias[n + 1];
                if (EPI == 0) {
                    *(__half2*)((__half*)Cc + obase + n) = __floats2half2_rn(v0, v1);
                } else if (EPI == 1) {
                    v0 = 0.5f * v0 * (1.0f + erff(v0 * 0.7071067811865476f));
                    v1 = 0.5f * v1 * (1.0f + erff(v1 * 0.7071067811865476f));
                    *(__half2*)((__half*)Cc + obase + n) = __floats2half2_rn(v0, v1);
                } else {
                    v0 += rbase[n];
                    v1 += rbase[n + 1];
                    *(float2*)((float*)Cc + obase + n) = make_float2(v0, v1);
                }
            }
        }
    }
}

// ---------------- SIMT windowed attention, 2 rows/warp-iter, vectorized loads ----------------
#define KSTR 36           // half2 per K row (32 + 4 pad) -> 144B rows, uint4-loadable
#define AT_QS   0                          // half2 [196][32]  25088 B
#define AT_VS   25088                      // half2 [196][32]  25088 B
#define AT_KS   50176                      // half2 [196][36]  28224 B
#define AT_RH   78400                      // float [27][66]    7128 B
#define AT_RW   85528                      // float [27][66]    7128 B
#define AT_PS   92656                      // float [8][2][200]12800 B
#define AT_RHW  105456                     // float [8][128]    4096 B
#define ATTN_SMEM_BYTES 109552

__global__ __launch_bounds__(256, 2)
void attn_kernel(const __half* __restrict__ qkv,
                 const float* __restrict__ relh,
                 const float* __restrict__ relw,
                 __half* __restrict__ attout) {
    extern __shared__ char smc[];
    __half2* qs2 = (__half2*)(smc + AT_QS);
    __half2* vs2 = (__half2*)(smc + AT_VS);
    __half2* ks2 = (__half2*)(smc + AT_KS);
    float* Rh  = (float*)(smc + AT_RH);
    float* Rw  = (float*)(smc + AT_RW);
    float* Ps  = (float*)(smc + AT_PS);
    float* rhw = (float*)(smc + AT_RHW);

    int blk = blockIdx.x;
    int bw = blk / NH, nh = blk % NH;
    int tid = threadIdx.x, lane = tid & 31, warp = tid >> 5;

    const __half* base = qkv + (size_t)bw * TOK * QKVN + nh * HD;
    for (int t4 = tid; t4 < TOK * 8; t4 += 256) {
        int t = t4 >> 3, cp4 = (t4 & 7) * 4;   // half2 index
        const __half* p = base + (size_t)t * QKVN + cp4 * 2;
        *(uint4*)(qs2 + t * 32 + cp4)   = *(const uint4*)(p);
        *(uint4*)(vs2 + t * 32 + cp4)   = *(const uint4*)(p + 2 * CDIM);
        *(uint4*)(ks2 + t * KSTR + cp4) = *(const uint4*)(p + CDIM);
    }
    for (int idx = tid; idx < 27 * 64; idx += 256) {
        int rr = idx >> 6, cc = idx & 63;
        Rh[rr * 66 + cc] = relh[idx];
        Rw[rr * 66 + cc] = relw[idx];
    }
    __syncthreads();

    const float scale = 0.125f;
    float* wr  = rhw + warp * 128;
    float* Ps0 = Ps + warp * 400;
    float* Ps1 = Ps0 + 200;

    for (int pr = warp; pr < 98; pr += 8) {
        int qi0 = 2 * pr, qi1 = qi0 + 1;

        // ---- rel-pos dots: lanes 0..13 -> row qi0; lanes 16..29 -> row qi1 ----
        {
            int row = (lane < 16) ? qi0 : qi1;
            int off = lane & 15;
            if (off < WS) {
                int i = row / WS, j = row % WS;
                const float* rhrow = Rh + (i - off + WS - 1) * 66;
                const float* rwrow = Rw + (j - off + WS - 1) * 66;
                const __half2* q2 = qs2 + row * 32;
                float rh = 0.f, rw = 0.f;
                #pragma unroll 8
                for (int cp = 0; cp < 32; cp++) {
                    float2 qf = __half22float2(q2[cp]);
                    float2 hh = *(const float2*)(rhrow + 2 * cp);
                    float2 wv = *(const float2*)(rwrow + 2 * cp);
                    rh = fmaf(qf.x, hh.x, fmaf(qf.y, hh.y, rh));
                    rw = fmaf(qf.x, wv.x, fmaf(qf.y, wv.y, rw));
                }
                int bofs = (lane < 16) ? 0 : 64;
                wr[bofs + off]      = rh;
                wr[bofs + 32 + off] = rw;
            }
        }
        __syncwarp();

        // ---- QK^T for both rows (K loaded/converted once) ----
        float a0[7], a1[7];
        #pragma unroll
        for (int m = 0; m < 7; m++) { a0[m] = 0.f; a1[m] = 0.f; }
        #pragma unroll
        for (int cb = 0; cb < 8; cb++) {
            uint4 q0v = *(const uint4*)(qs2 + qi0 * 32 + cb * 4);
            uint4 q1v = *(const uint4*)(qs2 + qi1 * 32 + cb * 4);
            const __half2* q0h = (const __half2*)&q0v;
            const __half2* q1h = (const __half2*)&q1v;
            float2 q0f[4], q1f[4];
            #pragma unroll
            for (int u = 0; u < 4; u++) { q0f[u] = __half22float2(q0h[u]); q1f[u] = __half22float2(q1h[u]); }
            #pragma unroll
            for (int m = 0; m < 7; m++) {
                int kj = lane + 32 * m;
                if (m < 6 || kj < TOK) {
                    uint4 kv = *(const uint4*)(ks2 + kj * KSTR + cb * 4);
                    const __half2* kh = (const __half2*)&kv;
                    #pragma unroll
                    for (int u = 0; u < 4; u++) {
                        float2 kf = __half22float2(kh[u]);
                        a0[m] = fmaf(q0f[u].x, kf.x, fmaf(q0f[u].y, kf.y, a0[m]));
                        a1[m] = fmaf(q1f[u].x, kf.x, fmaf(q1f[u].y, kf.y, a1[m]));
                    }
                }
            }
        }

        // ---- bias + softmax for both rows ----
        float s0[7], s1[7];
        #pragma unroll
        for (int m = 0; m < 7; m++) {
            int kj = lane + 32 * m;
            if (kj < TOK) {
                int kk = kj / WS, ll = kj % WS;
                s0[m] = a0[m] * scale + wr[kk]      + wr[32 + ll];
                s1[m] = a1[m] * scale + wr[64 + kk] + wr[96 + ll];
            } else { s0[m] = -1e30f; s1[m] = -1e30f; }
        }
        float mx0 = -1e30f, mx1 = -1e30f;
        #pragma unroll
        for (int m = 0; m < 7; m++) { mx0 = fmaxf(mx0, s0[m]); mx1 = fmaxf(mx1, s1[m]); }
        #pragma unroll
        for (int o = 16; o > 0; o >>= 1) {
            mx0 = fmaxf(mx0, __shfl_xor_sync(0xffffffffu, mx0, o));
            mx1 = fmaxf(mx1, __shfl_xor_sync(0xffffffffu, mx1, o));
        }
        float sum0 = 0.f, sum1 = 0.f;
        #pragma unroll
        for (int m = 0; m < 7; m++) {
            s0[m] = __expf(s0[m] - mx0); sum0 += s0[m];
            s1[m] = __expf(s1[m] - mx1); sum1 += s1[m];
        }
        #pragma unroll
        for (int o = 16; o > 0; o >>= 1) {
            sum0 += __shfl_xor_sync(0xffffffffu, sum0, o);
            sum1 += __shfl_xor_sync(0xffffffffu, sum1, o);
        }
        float inv0 = __frcp_rn(sum0), inv1 = __frcp_rn(sum1);
        #pragma unroll
        for (int m = 0; m < 7; m++) {
            int kj = lane + 32 * m;
            if (kj < TOK) { Ps0[kj] = s0[m] * inv0; Ps1[kj] = s1[m] * inv1; }
        }
        __syncwarp();

        // ---- P·V for both rows (V loaded/converted once; P via float4) ----
        float o00 = 0.f, o01 = 0.f, o10 = 0.f, o11 = 0.f;
        for (int kb = 0; kb < 49; kb++) {
            float4 p0 = *(const float4*)(Ps0 + kb * 4);
            float4 p1 = *(const float4*)(Ps1 + kb * 4);
            float2 v0 = __half22float2(vs2[(4 * kb + 0) * 32 + lane]);
            float2 v1 = __half22float2(vs2[(4 * kb + 1) * 32 + lane]);
            float2 v2 = __half22float2(vs2[(4 * kb + 2) * 32 + lane]);
            float2 v3 = __half22float2(vs2[(4 * kb + 3) * 32 + lane]);
            o00 = fmaf(p0.x, v0.x, o00); o01 = fmaf(p0.x, v0.y, o01);
            o10 = fmaf(p1.x, v0.x, o10); o11 = fmaf(p1.x, v0.y, o11);
            o00 = fmaf(p0.y, v1.x, o00); o01 = fmaf(p0.y, v1.y, o01);
            o10 = fmaf(p1.y, v1.x, o10); o11 = fmaf(p1.y, v1.y, o11);
            o00 = fmaf(p0.z, v2.x, o00); o01 = fmaf(p0.z, v2.y, o01);
            o10 = fmaf(p1.z, v2.x, o10); o11 = fmaf(p1.z, v2.y, o11);
            o00 = fmaf(p0.w, v3.x, o00); o01 = fmaf(p0.w, v3.y, o01);
            o10 = fmaf(p1.w, v3.x, o10); o11 = fmaf(p1.w, v3.y, o11);
        }
        __half* orow0 = attout + ((size_t)(bw * TOK + qi0)) * CDIM + nh * HD;
        __half* orow1 = attout + ((size_t)(bw * TOK + qi1)) * CDIM + nh * HD;
        *(__half2*)(orow0 + 2 * lane) = __floats2half2_rn(o00, o01);
        *(__half2*)(orow1 + 2 * lane) = __floats2half2_rn(o10, o11);
        __syncwarp();
    }
}

// ---------------- launch ----------------
extern "C" void kernel_launch(void* const* d_in, const int* in_sizes, int n_in,
                              void* d_out, int out_size) {
    const float* x       = (const float*)d_in[0];
    const float* ln1_g   = (const float*)d_in[1];
    const float* ln1_b   = (const float*)d_in[2];
    const float* w_qkv   = (const float*)d_in[3];
    const float* b_qkv   = (const float*)d_in[4];
    const float* w_proj  = (const float*)d_in[5];
    const float* b_proj  = (const float*)d_in[6];
    const float* relh    = (const float*)d_in[7];
    const float* relw    = (const float*)d_in[8];
    const float* ln2_g   = (const float*)d_in[9];
    const float* ln2_b   = (const float*)d_in[10];
    const float* w_fc1   = (const float*)d_in[11];
    const float* b_fc1   = (const float*)d_in[12];
    const float* w_fc2   = (const float*)d_in[13];
    const float* b_fc2   = (const float*)d_in[14];
    float* out = (float*)d_out;

    __half *win, *qkv, *att, *yln, *y1, *wqkv, *wproj, *wfc1, *wfc2;
    float *x2;
    cudaGetSymbolAddress((void**)&win, g_win);
    cudaGetSymbolAddress((void**)&qkv, g_qkv);
    cudaGetSymbolAddress((void**)&att, g_att);
    cudaGetSymbolAddress((void**)&x2,  g_x2);
    cudaGetSymbolAddress((void**)&yln, g_yln);
    cudaGetSymbolAddress((void**)&y1,  g_y1);
    cudaGetSymbolAddress((void**)&wqkv,  g_wqkv);
    cudaGetSymbolAddress((void**)&wproj, g_wproj);
    cudaGetSymbolAddress((void**)&wfc1,  g_wfc1);
    cudaGetSymbolAddress((void**)&wfc2,  g_wfc2);

    cudaFuncSetAttribute(attn_kernel, cudaFuncAttributeMaxDynamicSharedMemorySize, ATTN_SMEM_BYTES);
    cudaFuncSetAttribute(hgemm<0>, cudaFuncAttributeMaxDynamicSharedMemorySize, GEMM_SMEM_BYTES);
    cudaFuncSetAttribute(hgemm<1>, cudaFuncAttributeMaxDynamicSharedMemorySize, GEMM_SMEM_BYTES);
    cudaFuncSetAttribute(hgemm<2>, cudaFuncAttributeMaxDynamicSharedMemorySize, GEMM_SMEM_BYTES);
    cudaFuncSetAttribute(hgemm<3>, cudaFuncAttributeMaxDynamicSharedMemorySize, GEMM_SMEM_BYTES);

    // (1) weights -> half2 interleaved
    int wtot = W1T + W2T + W3T + W4T;
    w2h_all_kernel<<<(wtot + 255) / 256, 256>>>(w_qkv, w_proj, w_fc1, w_fc2,
                                                wqkv, wproj, wfc1, wfc2);

    // (2) LN1 + window partition
    ln1_win_kernel<<<(ROWS_WIN * 32 + 255) / 256, 256>>>(x, ln1_g, ln1_b, win);

    // (3) QKV GEMM -> half
    hgemm<0><<<dim3(QKVN / 128, (ROWS_WIN + 127) / 128), 256, GEMM_SMEM_BYTES>>>(
        win, wqkv, b_qkv, nullptr, qkv, ROWS_WIN, QKVN, CDIM);

    // (4) attention
    attn_kernel<<<BW * NH, 256, ATTN_SMEM_BYTES>>>(qkv, relh, relw, att);

    // (5) proj + window reverse + residual -> f32
    hgemm<2><<<dim3(CDIM / 128, (ROWS_WIN + 127) / 128), 256, GEMM_SMEM_BYTES>>>(
        att, wproj, b_proj, x, x2, ROWS_WIN, CDIM, CDIM);

    // (6) LN2 -> half
    ln2_kernel<<<(ROWS_IMG * 32 + 255) / 256, 256>>>(x2, ln2_g, ln2_b, yln);

    // (7) fc1 + gelu -> half
    hgemm<1><<<dim3(FFN / 128, ROWS_IMG / 128), 256, GEMM_SMEM_BYTES>>>(
        yln, wfc1, b_fc1, nullptr, y1, ROWS_IMG, FFN, CDIM);

    // (8) fc2 + residual -> out f32
    hgemm<3><<<dim3(CDIM / 128, ROWS_IMG / 128), 256, GEMM_SMEM_BYTES>>>(
        y1, wfc2, b_fc2, x2, out, ROWS_IMG, CDIM, FFN);
}